// round 5
// baseline (speedup 1.0000x reference)
#include <cuda_runtime.h>

// ---------------------------------------------------------------------------
// QRU (quaternion recurrent unit) forward.
// S=512, B=256, IN_Q=64, H=64, G=2H=128, 4H=256.
//
// Strategy: 128 persistent CTAs (1/SM), each owns 2 batch rows for all 512
// steps (rows are independent -> zero inter-CTA sync). Each step is two
// "quaternion dual-matmuls":
//   phase A: v = [x_s ; normalize(h)]      (per comp: 128-long)  -> ac (512)
//   phase B: v = [normalize(h) ; cand_t]                          -> upd (512)
// Weights are repacked once into stacked component layout W[c][k][g]
// (c=quaternion comp of the weight, k=0..127 stacked input, g=0..127 out col),
// 256KB per phase, streamed from L2 each step.
//
// Hamilton combine (y_q = sum_p sign(q,p) * d[p][M(q,p)][g]):
//   q=0(r): M=[0,1,2,3] S=[+,-,-,-]
//   q=1(i): M=[1,0,3,2] S=[+,+,-,+]
//   q=2(j): M=[2,3,0,1] S=[+,+,+,-]
//   q=3(k): M=[3,2,1,0] S=[+,-,+,+]
// ---------------------------------------------------------------------------

__device__ float g_WA[4 * 128 * 128];   // phase A weights: k<64 -> w_ih, k>=64 -> w_hh
__device__ float g_WB[4 * 128 * 128];   // phase B weights: k<64 -> wpick_h, k>=64 -> wpick_cand
__device__ float g_bA[512];             // b_ih + b_hh
__device__ float g_bB[512];             // b_pick_h + b_pick_cand

__constant__ int   c_M[16] = {0,1,2,3,  1,0,3,2,  2,3,0,1,  3,2,1,0};
__constant__ float c_S[16] = {1.f,-1.f,-1.f,-1.f,  1.f,1.f,-1.f,1.f,
                              1.f,1.f,1.f,-1.f,    1.f,-1.f,1.f,1.f};

// --- prep: repack weights + fold biases (runs once per launch, trivial) ----
__global__ void qru_prep(
    const float* __restrict__ wih_r, const float* __restrict__ wih_i,
    const float* __restrict__ wih_j, const float* __restrict__ wih_k,
    const float* __restrict__ whh_r, const float* __restrict__ whh_i,
    const float* __restrict__ whh_j, const float* __restrict__ whh_k,
    const float* __restrict__ wpc_r, const float* __restrict__ wpc_i,
    const float* __restrict__ wpc_j, const float* __restrict__ wpc_k,
    const float* __restrict__ wph_r, const float* __restrict__ wph_i,
    const float* __restrict__ wph_j, const float* __restrict__ wph_k,
    const float* __restrict__ b_ih, const float* __restrict__ b_hh,
    const float* __restrict__ b_ph, const float* __restrict__ b_pc)
{
    int i = blockIdx.x * blockDim.x + threadIdx.x;   // 131072 total
    int half = i >> 16;
    int j = i & 65535;
    int cc = j >> 14;
    int k  = (j >> 7) & 127;
    int gg = j & 127;
    const float* src;
    if (half == 0) {
        if (k < 64) src = (cc == 0 ? wih_r : cc == 1 ? wih_i : cc == 2 ? wih_j : wih_k);
        else        src = (cc == 0 ? whh_r : cc == 1 ? whh_i : cc == 2 ? whh_j : whh_k);
        g_WA[j] = src[(k & 63) * 128 + gg];
    } else {
        if (k < 64) src = (cc == 0 ? wph_r : cc == 1 ? wph_i : cc == 2 ? wph_j : wph_k);
        else        src = (cc == 0 ? wpc_r : cc == 1 ? wpc_i : cc == 2 ? wpc_j : wpc_k);
        g_WB[j] = src[(k & 63) * 128 + gg];
    }
    if (i < 512)            g_bA[i]       = b_ih[i] + b_hh[i];
    else if (i < 1024)      g_bB[i - 512] = b_ph[i - 512] + b_pc[i - 512];
}

// --- dot phase: thread = (c, ks, gv); computes d[p][row][4 g's] -------------
__device__ __forceinline__ void qdot(const float* __restrict__ v,     // [2][4][128]
                                     const float* __restrict__ W,     // [4][128][128]
                                     float* __restrict__ ds,
                                     int c, int ks, int gv)
{
    float acc[4][2][4];
#pragma unroll
    for (int p = 0; p < 4; ++p)
#pragma unroll
        for (int r = 0; r < 2; ++r)
#pragma unroll
            for (int i = 0; i < 4; ++i) acc[p][r][i] = 0.f;

    const float4* Wp = reinterpret_cast<const float4*>(W) + (c * 128 + ks * 32) * 32 + gv;
    const int k0 = ks * 32;

#pragma unroll 2
    for (int kb = 0; kb < 32; kb += 4) {
        float4 w0 = Wp[0];
        float4 w1 = Wp[32];
        float4 w2 = Wp[64];
        float4 w3 = Wp[96];
        Wp += 128;
#pragma unroll
        for (int p = 0; p < 4; ++p) {
#pragma unroll
            for (int r = 0; r < 2; ++r) {
                const float4 vv = *reinterpret_cast<const float4*>(v + (r * 4 + p) * 128 + k0 + kb);
                float* a = acc[p][r];
                a[0] = fmaf(vv.x, w0.x, a[0]); a[1] = fmaf(vv.x, w0.y, a[1]);
                a[2] = fmaf(vv.x, w0.z, a[2]); a[3] = fmaf(vv.x, w0.w, a[3]);
                a[0] = fmaf(vv.y, w1.x, a[0]); a[1] = fmaf(vv.y, w1.y, a[1]);
                a[2] = fmaf(vv.y, w1.z, a[2]); a[3] = fmaf(vv.y, w1.w, a[3]);
                a[0] = fmaf(vv.z, w2.x, a[0]); a[1] = fmaf(vv.z, w2.y, a[1]);
                a[2] = fmaf(vv.z, w2.z, a[2]); a[3] = fmaf(vv.z, w2.w, a[3]);
                a[0] = fmaf(vv.w, w3.x, a[0]); a[1] = fmaf(vv.w, w3.y, a[1]);
                a[2] = fmaf(vv.w, w3.z, a[2]); a[3] = fmaf(vv.w, w3.w, a[3]);
            }
        }
    }
#pragma unroll
    for (int p = 0; p < 4; ++p)
#pragma unroll
        for (int r = 0; r < 2; ++r) {
            float4 o = make_float4(acc[p][r][0], acc[p][r][1], acc[p][r][2], acc[p][r][3]);
            *reinterpret_cast<float4*>(ds + ((((p * 4 + c) * 4 + ks) * 2 + r) * 128) + gv * 4) = o;
        }
}

// --- sign combine: thread = (q, g) -----------------------------------------
__device__ __forceinline__ void qcombine(const float* __restrict__ ds,
                                         const float* __restrict__ bias,
                                         float* __restrict__ yb, int q, int g)
{
#pragma unroll
    for (int r = 0; r < 2; ++r) {
        float y = bias[q * 128 + g];
#pragma unroll
        for (int p = 0; p < 4; ++p) {
            const int   cm = c_M[q * 4 + p];
            const float sg = c_S[q * 4 + p];
            const float* dp = ds + ((p * 4 + cm) * 8 + r) * 128 + g;   // ks stride = 256
            float sum = dp[0] + dp[256] + dp[512] + dp[768];
            y = fmaf(sg, sum, y);
        }
        yb[r * 512 + q * 128 + g] = y;
    }
}

__global__ void __launch_bounds__(512, 1)
qru_main(const float* __restrict__ x, const float* __restrict__ hx,
         float* __restrict__ out, float* __restrict__ hT, int writeHT)
{
    extern __shared__ float smf[];
    float* ds = smf;              // 16384 : partial dots [p][c][ks][r][g]
    float* vA = smf + 16384;      //  1024 : phase A input  [r][p][128] = [x | h_n]
    float* vB = smf + 17408;      //  1024 : phase B input  [r][p][128] = [h_n | cand_t]
    float* yb = smf + 18432;      //  1024 : combine output [r][512]
    float* hb = smf + 19456;      //   512 : hidden carry   [r][256]

    const int t  = threadIdx.x;
    const int b0 = blockIdx.x * 2;
    const int c  = t >> 7;            // weight component (also q in combine)
    const int ks = (t >> 5) & 3;      // k-slice
    const int gv = t & 31;            // 4-wide g group
    const int g  = t & 127;           // combine column
    const int rr = t >> 8;            // x-load row
    const int idx = t & 255;          // x-load feature

    hb[rr * 256 + idx] = hx[(b0 + rr) * 256 + idx];
    __syncthreads();

    for (int s = 0; s < 512; ++s) {
        // (a) normalize h -> h_n into vA[k>=64] and vB[k<64]
        if (t < 128) {
            const int r = t >> 6, n = t & 63;
            float h0 = hb[r * 256 + n],        h1 = hb[r * 256 + 64 + n];
            float h2 = hb[r * 256 + 128 + n],  h3 = hb[r * 256 + 192 + n];
            float inv = 1.f / (sqrtf(h0 * h0 + h1 * h1 + h2 * h2 + h3 * h3) + 1e-4f);
            h0 *= inv; h1 *= inv; h2 *= inv; h3 *= inv;
            vA[(r * 4 + 0) * 128 + 64 + n] = h0; vA[(r * 4 + 1) * 128 + 64 + n] = h1;
            vA[(r * 4 + 2) * 128 + 64 + n] = h2; vA[(r * 4 + 3) * 128 + 64 + n] = h3;
            vB[(r * 4 + 0) * 128 + n] = h0;      vB[(r * 4 + 1) * 128 + n] = h1;
            vB[(r * 4 + 2) * 128 + n] = h2;      vB[(r * 4 + 3) * 128 + n] = h3;
        }
        // (b) load x_s into vA[k<64]
        {
            const int p = idx >> 6, k = idx & 63;
            vA[(rr * 4 + p) * 128 + k] = x[(size_t)(s * 256 + b0 + rr) * 256 + idx];
        }
        __syncthreads();

        // (c) phase A dots
        qdot(vA, g_WA, ds, c, ks, gv);
        __syncthreads();
        // (d) phase A combine -> ac in yb
        qcombine(ds, g_bA, yb, c, g);
        __syncthreads();

        // (e) amp gate + cand_t -> vB[k>=64]
        if (t < 128) {
            const int r = t >> 6, n = t & 63;
            float a0 = yb[r * 512 + n],        a1 = yb[r * 512 + 128 + n];
            float a2 = yb[r * 512 + 256 + n],  a3 = yb[r * 512 + 384 + n];
            float ag = sqrtf(a0 * a0 + a1 * a1 + a2 * a2 + a3 * a3);
            float q0 = yb[r * 512 + 64 + n]  * ag;
            float q1 = yb[r * 512 + 192 + n] * ag;
            float q2 = yb[r * 512 + 320 + n] * ag;
            float q3 = yb[r * 512 + 448 + n] * ag;
            float inv = 1.f / (sqrtf(q0 * q0 + q1 * q1 + q2 * q2 + q3 * q3) + 1e-4f);
            vB[(r * 4 + 0) * 128 + 64 + n] = q0 * inv;
            vB[(r * 4 + 1) * 128 + 64 + n] = q1 * inv;
            vB[(r * 4 + 2) * 128 + 64 + n] = q2 * inv;
            vB[(r * 4 + 3) * 128 + 64 + n] = q3 * inv;
        }
        __syncthreads();

        // (f) phase B dots
        qdot(vB, g_WB, ds, c, ks, gv);
        __syncthreads();
        // (g) phase B combine -> upd in yb
        qcombine(ds, g_bB, yb, c, g);
        __syncthreads();

        // (h) gates + new hidden state + output
        if (t < 128) {
            const int r = t >> 6, n = t & 63;
            float u0 = yb[r * 512 + n];
            float u2 = yb[r * 512 + 128 + n];
            float u4 = yb[r * 512 + 256 + n];
            float gh = sqrtf(u0 * u0 + 2.f * u2 * u2 + u4 * u4);   // i-comp reused, k dropped (faithful)
            float u1 = yb[r * 512 + 64 + n],  u3 = yb[r * 512 + 192 + n];
            float u5 = yb[r * 512 + 320 + n], u7 = yb[r * 512 + 448 + n];
            float gc = sqrtf(u1 * u1 + u3 * u3 + u5 * u5 + u7 * u7);
            float* orow = out + (size_t)(s * 256 + b0 + r) * 256;
#pragma unroll
            for (int p = 0; p < 4; ++p) {
                float hn = vB[(r * 4 + p) * 128 + n];        // normalized h
                float ct = vB[(r * 4 + p) * 128 + 64 + n];   // cand_t
                float av = fmaf(hn, gh, ct * gc);
                hb[r * 256 + p * 64 + n] = av;
                orow[p * 64 + n] = av;
            }
            if (writeHT && s == 511) {
#pragma unroll
                for (int p = 0; p < 4; ++p)
                    hT[(size_t)(b0 + r) * 256 + p * 64 + n] = hb[r * 256 + p * 64 + n];
            }
        }
        // no barrier needed: (h)->(a) hazards are same-thread; cross-thread
        // consumers are all behind the post-(b) barrier of the next step.
    }
}

extern "C" void kernel_launch(void* const* d_in, const int* in_sizes, int n_in,
                              void* d_out, int out_size)
{
    const float* x  = (const float*)d_in[0];
    const float* hx = (const float*)d_in[1];

    qru_prep<<<512, 256>>>(
        (const float*)d_in[2],  (const float*)d_in[3],  (const float*)d_in[4],  (const float*)d_in[5],
        (const float*)d_in[6],  (const float*)d_in[7],  (const float*)d_in[8],  (const float*)d_in[9],
        (const float*)d_in[10], (const float*)d_in[11], (const float*)d_in[12], (const float*)d_in[13],
        (const float*)d_in[14], (const float*)d_in[15], (const float*)d_in[16], (const float*)d_in[17],
        (const float*)d_in[18], (const float*)d_in[19], (const float*)d_in[20], (const float*)d_in[21]);

    float* out = (float*)d_out;
    long long base = 512LL * 256 * 256;
    int writeHT = (out_size >= base + 256 * 256) ? 1 : 0;
    float* hT = out + base;

    size_t smem = (16384 + 1024 + 1024 + 1024 + 512) * sizeof(float);  // 79872 B
    cudaFuncSetAttribute(qru_main, cudaFuncAttributeMaxDynamicSharedMemorySize, (int)smem);
    qru_main<<<128, 512, smem>>>(x, hx, out, hT, writeHT);
}